// round 7
// baseline (speedup 1.0000x reference)
#include <cuda_runtime.h>
#include <cuda_fp16.h>
#include <cstdint>

// ============================================================================
// CIN fused kernel, GB300 sm_103 (mma.sync + ldmatrix path).
// Per CTA (4 batches): out[n,o] = sum_k Zt[n,k] * W[o,k],  k=(h,m), n=(bl,d)
//   A = Zt built in REGISTERS: half2 x0 (resident) * h broadcast via HMUL2
//   B = W chunk (fp16 scratch) via cp.async + ldmatrix, double buffered
// K-chunk = 128 (four h rows per barrier round).  Warp tile: 32 n x 64 o.
// ============================================================================

#define DEVINL __device__ __forceinline__

constexpr int THREADS = 512;
constexpr int NCTA    = 128;
constexpr int NCH128  = 8 + 32 + 32;      // 72 k-chunks of 128

// smem layout (bytes)
constexpr int SM_SCORE = 0;                    // 4 floats
constexpr int SM_BIAS  = 64;                   // 384 floats
constexpr int SM_LW    = 1600;                 // 384 floats
constexpr int SM_W     = 3200;                 // 2 stages x 40960
constexpr int W_STAGE  = 40960;                // 4 sub-chunks x (128 rows x 80B)
constexpr int SM_H     = SM_W + 2 * W_STAGE;   // 85120
constexpr int H_ROWF   = 132;                  // floats per h row (pad)
constexpr int SMEM_BYTES = SM_H + 256 * H_ROWF * 4;   // 220288

// device scratch: fp16 weights
__device__ __align__(16) __half g_W0h[128 * 1024];
__device__ __align__(16) __half g_W1h[128 * 4096];
__device__ __align__(16) __half g_W2h[128 * 4096];

// ---------------- helpers ----------------
DEVINL uint32_t smem_u32(const void* p) {
    uint32_t a;
    asm("{ .reg .u64 t; cvta.to.shared.u64 t, %1; cvt.u32.u64 %0, t; }"
        : "=r"(a) : "l"(p));
    return a;
}

DEVINL void cp_async16(uint32_t dst, const void* src) {
    asm volatile("cp.async.cg.shared.global [%0], [%1], 16;"
                 :: "r"(dst), "l"(src) : "memory");
}
DEVINL void cp_commit() { asm volatile("cp.async.commit_group;" ::: "memory"); }
DEVINL void cp_wait0()  { asm volatile("cp.async.wait_group 0;" ::: "memory"); }

DEVINL uint32_t h2u(__half2 v) { return *reinterpret_cast<uint32_t*>(&v); }

DEVINL void ldsm_x4(uint32_t& b0, uint32_t& b1, uint32_t& b2, uint32_t& b3,
                    uint32_t addr) {
    asm volatile("ldmatrix.sync.aligned.m8n8.x4.shared.b16 {%0,%1,%2,%3}, [%4];"
                 : "=r"(b0), "=r"(b1), "=r"(b2), "=r"(b3) : "r"(addr));
}

DEVINL void mma16816(float* c, uint32_t a0, uint32_t a1, uint32_t a2, uint32_t a3,
                     uint32_t b0, uint32_t b1) {
    asm volatile(
        "mma.sync.aligned.m16n8k16.row.col.f32.f16.f16.f32 "
        "{%0,%1,%2,%3}, {%4,%5,%6,%7}, {%8,%9}, {%0,%1,%2,%3};"
        : "+f"(c[0]), "+f"(c[1]), "+f"(c[2]), "+f"(c[3])
        : "r"(a0), "r"(a1), "r"(a2), "r"(a3), "r"(b0), "r"(b1));
}

// ============================================================================
// prep: fp32 W -> fp16 scratch
// ============================================================================
__global__ void cin_w2h(const float* __restrict__ W0,
                        const float* __restrict__ W1,
                        const float* __restrict__ W2) {
    int i = blockIdx.x * blockDim.x + threadIdx.x;
    constexpr int S0 = 128 * 1024;
    constexpr int S1 = 128 * 4096;
    if (i < S0)               g_W0h[i] = __float2half_rn(W0[i]);
    else if (i < S0 + S1)     g_W1h[i - S0] = __float2half_rn(W1[i - S0]);
    else if (i < S0 + 2 * S1) g_W2h[i - S0 - S1] = __float2half_rn(W2[i - S0 - S1]);
}

// W chunk-128 fetch: 4 sub-chunks of 32 k-cols; thread -> row tid>>2, seg tid&3
DEVINL void issue_w128(int gc, uint32_t wdst, int tid) {
    const __half* src; int kw;
    if (gc < 8)       { src = g_W0h + gc * 128;        kw = 1024; }
    else if (gc < 40) { src = g_W1h + (gc - 8) * 128;  kw = 4096; }
    else              { src = g_W2h + (gc - 40) * 128; kw = 4096; }
    int r = tid >> 2, j = tid & 3;
    const __half* s0 = src + (size_t)r * kw + j * 8;
    uint32_t d0 = wdst + (uint32_t)r * 80 + (uint32_t)j * 16;
#pragma unroll
    for (int s = 0; s < 4; s++)
        cp_async16(d0 + (uint32_t)s * 10240u, s0 + s * 32);
    cp_commit();
}

// ============================================================================
// main fused kernel: 1 CTA = 4 batches (256 n-rows x 128 o), 3 layers + score
// ============================================================================
__global__ __launch_bounds__(THREADS, 1)
void cin_main(const float* __restrict__ x0g,
              const float* __restrict__ bias0,
              const float* __restrict__ bias1,
              const float* __restrict__ bias2,
              const float* __restrict__ lwp,
              const float* __restrict__ lbp,
              float* __restrict__ outp) {
    extern __shared__ char smemc[];
    const uint32_t sb = smem_u32(smemc);
    const int tid  = threadIdx.x;
    const int w    = tid >> 5;
    const int lane = tid & 31;
    const int b_base = blockIdx.x * 4;

    // prefetch first W chunk immediately
    issue_w128(0, sb + SM_W, tid);

    // bias / lw to smem
    {
        const float* bptrs[3] = { bias0, bias1, bias2 };
        float* biasS = (float*)(smemc + SM_BIAS);
        float* lwS   = (float*)(smemc + SM_LW);
        for (int i = tid; i < 384; i += THREADS) {
            biasS[i] = bptrs[i >> 7][i & 127];
            lwS[i]   = lwp[i];
        }
    }
    if (tid < 4) ((float*)(smemc + SM_SCORE))[tid] = 0.0f;

    float* hS = (float*)(smemc + SM_H);
    // layer-0 h: h[n][m] = x0[bl][m][d],  n = bl*64 + d
    for (int i = tid; i < 256 * 32; i += THREADS) {
        int m = i >> 8, n = i & 255;
        hS[(size_t)n * H_ROWF + m] =
            x0g[(((size_t)(b_base + (n >> 6))) * 32 + m) * 64 + (n & 63)];
    }

    // ---- per-thread geometry ----
    const int wn = w & 7;           // n block (32 rows)
    const int wo = w >> 3;          // o half (64 outputs)
    const int r  = lane >> 2;
    const int q  = lane & 3;
    const int bl = wn >> 1;
    const int dbase = ((wn & 1) << 5) + r;

    // x0 as half2 registers: x0h[j][i] = {x0[2q+8i], x0[2q+8i+1]} at d_j
    __half2 x0h[4][4];
    {
        const float* xb = x0g + ((size_t)(b_base + bl) * 32) * 64;
#pragma unroll
        for (int j = 0; j < 4; j++) {
            int dj = dbase + 8 * j;
#pragma unroll
            for (int i = 0; i < 4; i++) {
                int m = 2 * q + 8 * i;
                x0h[j][i] = __floats2half2_rn(xb[(size_t)m * 64 + dj],
                                              xb[(size_t)(m + 1) * 64 + dj]);
            }
        }
    }

    // h row pointers (rows n_j = 32*wn + r + 8j)
    float* hrow0 = hS + (size_t)(32 * wn + r) * H_ROWF;
    float* hrow1 = hrow0 + 8 * H_ROWF;
    float* hrow2 = hrow0 + 16 * H_ROWF;
    float* hrow3 = hrow0 + 24 * H_ROWF;

    // ldmatrix fragment base (within this warp's 64-o half)
    const int mi = lane >> 3;
    const uint32_t lm_base = (uint32_t)(wo * 5120 +
                             ((mi >> 1) * 8 + (lane & 7)) * 80 + (mi & 1) * 16);

    float acc[16][4];
#pragma unroll
    for (int t = 0; t < 16; t++)
#pragma unroll
        for (int c = 0; c < 4; c++) acc[t][c] = 0.0f;

    float score = 0.0f;
    int gc = 0;
    __syncthreads();   // h init + score init visible

    for (int lay = 0; lay < 3; lay++) {
        const int nch = (lay == 0) ? 8 : 32;
        for (int ch = 0; ch < nch; ch++, gc++) {
            const int buf = gc & 1;
            cp_wait0();
            __syncthreads();                 // W[buf] visible; prev uses done
            if (gc + 1 < NCH128)
                issue_w128(gc + 1, sb + SM_W + (uint32_t)(buf ^ 1) * W_STAGE, tid);

            const uint32_t wbu = sb + SM_W + (uint32_t)buf * W_STAGE + lm_base;

            // h values for this chunk's four k-rows (hh = 4ch..4ch+3), 4 n-rows
            float4 hf0 = *(const float4*)(hrow0 + 4 * ch);
            float4 hf1 = *(const float4*)(hrow1 + 4 * ch);
            float4 hf2 = *(const float4*)(hrow2 + 4 * ch);
            float4 hf3 = *(const float4*)(hrow3 + 4 * ch);

            auto do_sub = [&](float c0, float c1, float c2, float c3, int sub) {
                __half2 hb0 = __half2half2(__float2half_rn(c0));
                __half2 hb1 = __half2half2(__float2half_rn(c1));
                __half2 hb2 = __half2half2(__float2half_rn(c2));
                __half2 hb3 = __half2half2(__float2half_rn(c3));
#pragma unroll
                for (int sh = 0; sh < 2; sh++) {
                    uint32_t a00 = h2u(__hmul2(hb0, x0h[0][2 * sh]));
                    uint32_t a01 = h2u(__hmul2(hb1, x0h[1][2 * sh]));
                    uint32_t a02 = h2u(__hmul2(hb0, x0h[0][2 * sh + 1]));
                    uint32_t a03 = h2u(__hmul2(hb1, x0h[1][2 * sh + 1]));
                    uint32_t a10 = h2u(__hmul2(hb2, x0h[2][2 * sh]));
                    uint32_t a11 = h2u(__hmul2(hb3, x0h[3][2 * sh]));
                    uint32_t a12 = h2u(__hmul2(hb2, x0h[2][2 * sh + 1]));
                    uint32_t a13 = h2u(__hmul2(hb3, x0h[3][2 * sh + 1]));
                    const uint32_t lma = wbu + (uint32_t)sub * 10240u +
                                         (uint32_t)sh * 32u;
#pragma unroll
                    for (int g = 0; g < 4; g++) {
                        uint32_t b0, b1, b2, b3;
                        ldsm_x4(b0, b1, b2, b3, lma + (uint32_t)g * 1280);
                        mma16816(acc[2 * g],         a00, a01, a02, a03, b0, b1);
                        mma16816(acc[2 * g + 1],     a00, a01, a02, a03, b2, b3);
                        mma16816(acc[8 + 2 * g],     a10, a11, a12, a13, b0, b1);
                        mma16816(acc[8 + 2 * g + 1], a10, a11, a12, a13, b2, b3);
                    }
                }
            };
            do_sub(hf0.x, hf1.x, hf2.x, hf3.x, 0);
            do_sub(hf0.y, hf1.y, hf2.y, hf3.y, 1);
            do_sub(hf0.z, hf1.z, hf2.z, hf3.z, 2);
            do_sub(hf0.w, hf1.w, hf2.w, hf3.w, 3);
        }

        // -------- epilogue --------
        __syncthreads();   // all warps done reading h for this layer
        {
            const float* biasS = (const float*)(smemc + SM_BIAS) + lay * 128;
            const float* lwS   = (const float*)(smemc + SM_LW) + lay * 128;
            float sc = 0.0f;
#pragma unroll
            for (int T = 0; T < 2; T++) {
                float* ha  = T ? hrow2 : hrow0;
                float* hb2 = T ? hrow3 : hrow1;
#pragma unroll
                for (int go = 0; go < 8; go++) {
                    const int t = 8 * T + go;
                    const int o = 64 * wo + 8 * go + 2 * q;
                    const float bv0 = biasS[o], bv1 = biasS[o + 1];
                    float v00 = fmaxf(acc[t][0] + bv0, 0.0f);
                    float v01 = fmaxf(acc[t][1] + bv1, 0.0f);
                    float v10 = fmaxf(acc[t][2] + bv0, 0.0f);
                    float v11 = fmaxf(acc[t][3] + bv1, 0.0f);
                    sc += (v00 + v10) * lwS[o] + (v01 + v11) * lwS[o + 1];
                    if (lay < 2) {
                        *(float2*)(ha + o)  = make_float2(v00, v01);
                        *(float2*)(hb2 + o) = make_float2(v10, v11);
                    }
                    acc[t][0] = acc[t][1] = acc[t][2] = acc[t][3] = 0.0f;
                }
            }
            score += sc;
        }
    }

    // warp-reduce score, accumulate per-batch
#pragma unroll
    for (int off = 16; off; off >>= 1)
        score += __shfl_xor_sync(0xFFFFFFFFu, score, off);
    if (lane == 0) atomicAdd((float*)(smemc + SM_SCORE) + bl, score);
    __syncthreads();

    if (tid < 4) outp[b_base + tid] = ((float*)(smemc + SM_SCORE))[tid] + lbp[0];
}

extern "C" void kernel_launch(void* const* d_in, const int* in_sizes, int n_in,
                              void* d_out, int out_size) {
    const float* x0 = (const float*)d_in[0];
    const float* W0 = (const float*)d_in[1];
    const float* b0 = (const float*)d_in[2];
    const float* W1 = (const float*)d_in[3];
    const float* b1 = (const float*)d_in[4];
    const float* W2 = (const float*)d_in[5];
    const float* b2 = (const float*)d_in[6];
    const float* lw = (const float*)d_in[7];
    const float* lb = (const float*)d_in[8];
    float* outp = (float*)d_out;

    constexpr int TOTW = 128 * (1024 + 4096 + 4096);
    cin_w2h<<<(TOTW + 1023) / 1024, 1024>>>(W0, W1, W2);

    static_assert(SMEM_BYTES <= 227 * 1024, "smem");
    cudaFuncSetAttribute(cin_main, cudaFuncAttributeMaxDynamicSharedMemorySize,
                         SMEM_BYTES);
    cin_main<<<NCTA, THREADS, SMEM_BYTES>>>(x0, b0, b1, b2, lw, lb, outp);
}

// round 8
// speedup vs baseline: 1.5183x; 1.5183x over previous
#include <cuda_runtime.h>
#include <cuda_fp16.h>
#include <cstdint>

// ============================================================================
// CIN fused kernel, GB300 sm_103 (mma.sync + ldmatrix path).
// Per CTA (4 batches): out[n,o] = sum_k Zt[n,k] * W[o,k],  k=(h,m), n=(bl,d)
//   A = Zt built in REGISTERS: half2 x0 (resident) * h broadcast via HMUL2
//   B = W chunk (fp16 scratch) via cp.async + ldmatrix
// K-chunk = 64; 4-stage W ring; one __syncthreads per 2 chunks.
// Warp tile: 32 n x 64 o. Grid 128 x 512.
// ============================================================================

#define DEVINL __device__ __forceinline__

constexpr int THREADS = 512;
constexpr int NCTA    = 128;
constexpr int NCH64   = 16 + 64 + 64;     // 144 k-chunks of 64

// smem layout (bytes)
constexpr int SM_SCORE = 0;                    // 4 floats
constexpr int SM_BIAS  = 64;                   // 384 floats
constexpr int SM_LW    = 1600;                 // 384 floats
constexpr int SM_W     = 3200;                 // 4 stages x 20480
constexpr int W_STAGE  = 20480;                // 2 sub-chunks x (128 rows x 80B)
constexpr int SM_H     = SM_W + 4 * W_STAGE;   // 85120
constexpr int H_ROWF   = 132;                  // floats per h row (pad)
constexpr int SMEM_BYTES = SM_H + 256 * H_ROWF * 4;   // 220288

// device scratch: fp16 weights
__device__ __align__(16) __half g_W0h[128 * 1024];
__device__ __align__(16) __half g_W1h[128 * 4096];
__device__ __align__(16) __half g_W2h[128 * 4096];

// ---------------- helpers ----------------
DEVINL uint32_t smem_u32(const void* p) {
    uint32_t a;
    asm("{ .reg .u64 t; cvta.to.shared.u64 t, %1; cvt.u32.u64 %0, t; }"
        : "=r"(a) : "l"(p));
    return a;
}

DEVINL void cp_async16(uint32_t dst, const void* src) {
    asm volatile("cp.async.cg.shared.global [%0], [%1], 16;"
                 :: "r"(dst), "l"(src) : "memory");
}
DEVINL void cp_commit() { asm volatile("cp.async.commit_group;" ::: "memory"); }
DEVINL void cp_wait0()  { asm volatile("cp.async.wait_group 0;" ::: "memory"); }

DEVINL uint32_t h2u(__half2 v) { return *reinterpret_cast<uint32_t*>(&v); }

DEVINL void ldsm_x4(uint32_t& b0, uint32_t& b1, uint32_t& b2, uint32_t& b3,
                    uint32_t addr) {
    asm volatile("ldmatrix.sync.aligned.m8n8.x4.shared.b16 {%0,%1,%2,%3}, [%4];"
                 : "=r"(b0), "=r"(b1), "=r"(b2), "=r"(b3) : "r"(addr));
}

DEVINL void mma16816(float* c, uint32_t a0, uint32_t a1, uint32_t a2, uint32_t a3,
                     uint32_t b0, uint32_t b1) {
    asm volatile(
        "mma.sync.aligned.m16n8k16.row.col.f32.f16.f16.f32 "
        "{%0,%1,%2,%3}, {%4,%5,%6,%7}, {%8,%9}, {%0,%1,%2,%3};"
        : "+f"(c[0]), "+f"(c[1]), "+f"(c[2]), "+f"(c[3])
        : "r"(a0), "r"(a1), "r"(a2), "r"(a3), "r"(b0), "r"(b1));
}

// ============================================================================
// prep: fp32 W -> fp16 scratch
// ============================================================================
__global__ void cin_w2h(const float* __restrict__ W0,
                        const float* __restrict__ W1,
                        const float* __restrict__ W2) {
    int i = blockIdx.x * blockDim.x + threadIdx.x;
    constexpr int S0 = 128 * 1024;
    constexpr int S1 = 128 * 4096;
    if (i < S0)               g_W0h[i] = __float2half_rn(W0[i]);
    else if (i < S0 + S1)     g_W1h[i - S0] = __float2half_rn(W1[i - S0]);
    else if (i < S0 + 2 * S1) g_W2h[i - S0 - S1] = __float2half_rn(W2[i - S0 - S1]);
}

// W chunk-64 fetch: 2 sub-chunks of 32 k-cols; thread -> row tid>>2, seg tid&3
DEVINL void issue_w64(int gc, uint32_t wdst, int tid) {
    const __half* src; int kw;
    if (gc < 16)      { src = g_W0h + gc * 64;         kw = 1024; }
    else if (gc < 80) { src = g_W1h + (gc - 16) * 64;  kw = 4096; }
    else              { src = g_W2h + (gc - 80) * 64;  kw = 4096; }
    int r = tid >> 2, j = tid & 3;
    const __half* s0 = src + (size_t)r * kw + j * 8;
    uint32_t d0 = wdst + (uint32_t)r * 80 + (uint32_t)j * 16;
    cp_async16(d0, s0);
    cp_async16(d0 + 10240u, s0 + 32);
    cp_commit();
}

// ============================================================================
// main fused kernel: 1 CTA = 4 batches (256 n-rows x 128 o), 3 layers + score
// ============================================================================
__global__ __launch_bounds__(THREADS, 1)
void cin_main(const float* __restrict__ x0g,
              const float* __restrict__ bias0,
              const float* __restrict__ bias1,
              const float* __restrict__ bias2,
              const float* __restrict__ lwp,
              const float* __restrict__ lbp,
              float* __restrict__ outp) {
    extern __shared__ char smemc[];
    const uint32_t sb = smem_u32(smemc);
    const int tid  = threadIdx.x;
    const int w    = tid >> 5;
    const int lane = tid & 31;
    const int b_base = blockIdx.x * 4;

    // prefetch chunks 0 and 1 into stages 0 and 1
    issue_w64(0, sb + SM_W, tid);
    issue_w64(1, sb + SM_W + W_STAGE, tid);

    // bias / lw to smem
    {
        const float* bptrs[3] = { bias0, bias1, bias2 };
        float* biasS = (float*)(smemc + SM_BIAS);
        float* lwS   = (float*)(smemc + SM_LW);
        for (int i = tid; i < 384; i += THREADS) {
            biasS[i] = bptrs[i >> 7][i & 127];
            lwS[i]   = lwp[i];
        }
    }
    if (tid < 4) ((float*)(smemc + SM_SCORE))[tid] = 0.0f;

    float* hS = (float*)(smemc + SM_H);
    // layer-0 h: h[n][m] = x0[bl][m][d],  n = bl*64 + d
    for (int i = tid; i < 256 * 32; i += THREADS) {
        int m = i >> 8, n = i & 255;
        hS[(size_t)n * H_ROWF + m] =
            x0g[(((size_t)(b_base + (n >> 6))) * 32 + m) * 64 + (n & 63)];
    }

    // ---- per-thread geometry ----
    const int wn = w & 7;           // n block (32 rows)
    const int wo = w >> 3;          // o half (64 outputs)
    const int r  = lane >> 2;
    const int q  = lane & 3;
    const int bl = wn >> 1;
    const int dbase = ((wn & 1) << 5) + r;

    // x0 as half2 registers: x0h[j][i] = {x0[2q+8i], x0[2q+8i+1]} at d_j
    __half2 x0h[4][4];
    {
        const float* xb = x0g + ((size_t)(b_base + bl) * 32) * 64;
#pragma unroll
        for (int j = 0; j < 4; j++) {
            int dj = dbase + 8 * j;
#pragma unroll
            for (int i = 0; i < 4; i++) {
                int m = 2 * q + 8 * i;
                x0h[j][i] = __floats2half2_rn(xb[(size_t)m * 64 + dj],
                                              xb[(size_t)(m + 1) * 64 + dj]);
            }
        }
    }

    // h row pointers (rows n_j = 32*wn + r + 8j)
    float* hrow0 = hS + (size_t)(32 * wn + r) * H_ROWF;
    float* hrow1 = hrow0 + 8 * H_ROWF;
    float* hrow2 = hrow0 + 16 * H_ROWF;
    float* hrow3 = hrow0 + 24 * H_ROWF;

    // ldmatrix fragment base (within this warp's 64-o half)
    const int mi = lane >> 3;
    const uint32_t lm_base = (uint32_t)(wo * 5120 +
                             ((mi >> 1) * 8 + (lane & 7)) * 80 + (mi & 1) * 16);

    float acc[16][4];
#pragma unroll
    for (int t = 0; t < 16; t++)
#pragma unroll
        for (int c = 0; c < 4; c++) acc[t][c] = 0.0f;

    float score = 0.0f;
    int gc = 0;
    __syncthreads();   // h init + score init visible

    // per-chunk compute: k-rows hh = 2*chl, 2*chl+1 from W stage at wbu
    auto compute_chunk = [&](int chl, uint32_t wbu) {
        float2 hf0 = *(const float2*)(hrow0 + 2 * chl);
        float2 hf1 = *(const float2*)(hrow1 + 2 * chl);
        float2 hf2 = *(const float2*)(hrow2 + 2 * chl);
        float2 hf3 = *(const float2*)(hrow3 + 2 * chl);
        __half2 hb[4][2];
        hb[0][0] = __half2half2(__float2half_rn(hf0.x));
        hb[0][1] = __half2half2(__float2half_rn(hf0.y));
        hb[1][0] = __half2half2(__float2half_rn(hf1.x));
        hb[1][1] = __half2half2(__float2half_rn(hf1.y));
        hb[2][0] = __half2half2(__float2half_rn(hf2.x));
        hb[2][1] = __half2half2(__float2half_rn(hf2.y));
        hb[3][0] = __half2half2(__float2half_rn(hf3.x));
        hb[3][1] = __half2half2(__float2half_rn(hf3.y));

#pragma unroll
        for (int s = 0; s < 4; s++) {
            const int sub = s >> 1;      // which k-row of the pair
            const int sh  = s & 1;       // m half: [0,16) or [16,32)
            uint32_t a00 = h2u(__hmul2(hb[0][sub], x0h[0][2 * sh]));
            uint32_t a01 = h2u(__hmul2(hb[1][sub], x0h[1][2 * sh]));
            uint32_t a02 = h2u(__hmul2(hb[0][sub], x0h[0][2 * sh + 1]));
            uint32_t a03 = h2u(__hmul2(hb[1][sub], x0h[1][2 * sh + 1]));
            uint32_t a10 = h2u(__hmul2(hb[2][sub], x0h[2][2 * sh]));
            uint32_t a11 = h2u(__hmul2(hb[3][sub], x0h[3][2 * sh]));
            uint32_t a12 = h2u(__hmul2(hb[2][sub], x0h[2][2 * sh + 1]));
            uint32_t a13 = h2u(__hmul2(hb[3][sub], x0h[3][2 * sh + 1]));
            const uint32_t lma = wbu + (uint32_t)sub * 10240u +
                                 (uint32_t)sh * 32u;
#pragma unroll
            for (int g = 0; g < 4; g++) {
                uint32_t b0, b1, b2, b3;
                ldsm_x4(b0, b1, b2, b3, lma + (uint32_t)g * 1280);
                mma16816(acc[2 * g],         a00, a01, a02, a03, b0, b1);
                mma16816(acc[2 * g + 1],     a00, a01, a02, a03, b2, b3);
                mma16816(acc[8 + 2 * g],     a10, a11, a12, a13, b0, b1);
                mma16816(acc[8 + 2 * g + 1], a10, a11, a12, a13, b2, b3);
            }
        }
    };

    for (int lay = 0; lay < 3; lay++) {
        const int npair = (lay == 0) ? 8 : 32;     // chunk pairs per layer
        for (int pr = 0; pr < npair; pr++, gc += 2) {
            cp_wait0();
            __syncthreads();     // stages gc%4,(gc+1)%4 visible; pair gc-2 done
            if (gc + 2 < NCH64)
                issue_w64(gc + 2,
                          sb + SM_W + (uint32_t)((gc + 2) & 3) * W_STAGE, tid);
            if (gc + 3 < NCH64)
                issue_w64(gc + 3,
                          sb + SM_W + (uint32_t)((gc + 3) & 3) * W_STAGE, tid);

            const uint32_t wbu0 = sb + SM_W + (uint32_t)(gc & 3) * W_STAGE
                                  + lm_base;
            const uint32_t wbu1 = sb + SM_W + (uint32_t)((gc + 1) & 3) * W_STAGE
                                  + lm_base;
            compute_chunk(2 * pr,     wbu0);
            compute_chunk(2 * pr + 1, wbu1);
        }

        // -------- epilogue --------
        __syncthreads();   // all warps done reading h for this layer
        {
            const float* biasS = (const float*)(smemc + SM_BIAS) + lay * 128;
            const float* lwS   = (const float*)(smemc + SM_LW) + lay * 128;
            float sc = 0.0f;
#pragma unroll
            for (int T = 0; T < 2; T++) {
                float* ha  = T ? hrow2 : hrow0;
                float* hb2 = T ? hrow3 : hrow1;
#pragma unroll
                for (int go = 0; go < 8; go++) {
                    const int t = 8 * T + go;
                    const int o = 64 * wo + 8 * go + 2 * q;
                    const float bv0 = biasS[o], bv1 = biasS[o + 1];
                    float v00 = fmaxf(acc[t][0] + bv0, 0.0f);
                    float v01 = fmaxf(acc[t][1] + bv1, 0.0f);
                    float v10 = fmaxf(acc[t][2] + bv0, 0.0f);
                    float v11 = fmaxf(acc[t][3] + bv1, 0.0f);
                    sc += (v00 + v10) * lwS[o] + (v01 + v11) * lwS[o + 1];
                    if (lay < 2) {
                        *(float2*)(ha + o)  = make_float2(v00, v01);
                        *(float2*)(hb2 + o) = make_float2(v10, v11);
                    }
                    acc[t][0] = acc[t][1] = acc[t][2] = acc[t][3] = 0.0f;
                }
            }
            score += sc;
        }
        // h writes ordered before next layer's reads by next pair's barrier
    }

    // warp-reduce score, accumulate per-batch
#pragma unroll
    for (int off = 16; off; off >>= 1)
        score += __shfl_xor_sync(0xFFFFFFFFu, score, off);
    if (lane == 0) atomicAdd((float*)(smemc + SM_SCORE) + bl, score);
    __syncthreads();

    if (tid < 4) outp[b_base + tid] = ((float*)(smemc + SM_SCORE))[tid] + lbp[0];
}

extern "C" void kernel_launch(void* const* d_in, const int* in_sizes, int n_in,
                              void* d_out, int out_size) {
    const float* x0 = (const float*)d_in[0];
    const float* W0 = (const float*)d_in[1];
    const float* b0 = (const float*)d_in[2];
    const float* W1 = (const float*)d_in[3];
    const float* b1 = (const float*)d_in[4];
    const float* W2 = (const float*)d_in[5];
    const float* b2 = (const float*)d_in[6];
    const float* lw = (const float*)d_in[7];
    const float* lb = (const float*)d_in[8];
    float* outp = (float*)d_out;

    constexpr int TOTW = 128 * (1024 + 4096 + 4096);
    cin_w2h<<<(TOTW + 1023) / 1024, 1024>>>(W0, W1, W2);

    static_assert(SMEM_BYTES <= 227 * 1024, "smem");
    cudaFuncSetAttribute(cin_main, cudaFuncAttributeMaxDynamicSharedMemorySize,
                         SMEM_BYTES);
    cin_main<<<NCTA, THREADS, SMEM_BYTES>>>(x0, b0, b1, b2, lw, lb, outp);
}

// round 9
// speedup vs baseline: 1.5278x; 1.0063x over previous
#include <cuda_runtime.h>
#include <cuda_fp16.h>
#include <cstdint>

// ============================================================================
// CIN fused kernel, GB300 sm_103 (mma.sync + ldmatrix path).
// Per CTA (4 batches): out[n,o] = sum_k Zt[n,k] * W[o,k],  k=(h,m), n=(bl,d)
//   A = Zt built in REGISTERS: half2 x0 (resident) * h broadcast via HMUL2
//   B = W chunk (fp16 scratch) via cp.async + ldmatrix, ldsm PIPELINED 1 ahead
// K-chunk = 64; 4-stage W ring; one __syncthreads per 2 chunks.
// Warp tile: 32 n x 64 o. Grid 128 x 512.
// ============================================================================

#define DEVINL __device__ __forceinline__

constexpr int THREADS = 512;
constexpr int NCTA    = 128;
constexpr int NCH64   = 16 + 64 + 64;     // 144 k-chunks of 64

// smem layout (bytes)
constexpr int SM_SCORE = 0;                    // 4 floats
constexpr int SM_BIAS  = 64;                   // 384 floats
constexpr int SM_LW    = 1600;                 // 384 floats
constexpr int SM_W     = 3200;                 // 4 stages x 20480
constexpr int W_STAGE  = 20480;                // 2 sub-chunks x (128 rows x 80B)
constexpr int SM_H     = SM_W + 4 * W_STAGE;   // 85120
constexpr int H_ROWF   = 132;                  // floats per h row (pad)
constexpr int SMEM_BYTES = SM_H + 256 * H_ROWF * 4;   // 220288

// device scratch: fp16 weights
__device__ __align__(16) __half g_W0h[128 * 1024];
__device__ __align__(16) __half g_W1h[128 * 4096];
__device__ __align__(16) __half g_W2h[128 * 4096];

// ---------------- helpers ----------------
DEVINL uint32_t smem_u32(const void* p) {
    uint32_t a;
    asm("{ .reg .u64 t; cvta.to.shared.u64 t, %1; cvt.u32.u64 %0, t; }"
        : "=r"(a) : "l"(p));
    return a;
}

DEVINL void cp_async16(uint32_t dst, const void* src) {
    asm volatile("cp.async.cg.shared.global [%0], [%1], 16;"
                 :: "r"(dst), "l"(src) : "memory");
}
DEVINL void cp_commit() { asm volatile("cp.async.commit_group;" ::: "memory"); }
DEVINL void cp_wait0()  { asm volatile("cp.async.wait_group 0;" ::: "memory"); }

DEVINL uint32_t h2u(__half2 v) { return *reinterpret_cast<uint32_t*>(&v); }

DEVINL void ldsm_x4(uint32_t* b, uint32_t addr) {
    asm volatile("ldmatrix.sync.aligned.m8n8.x4.shared.b16 {%0,%1,%2,%3}, [%4];"
                 : "=r"(b[0]), "=r"(b[1]), "=r"(b[2]), "=r"(b[3]) : "r"(addr));
}

// non-volatile: pure register op, deps carried by constraints -> ptxas may
// schedule freely around the pipelined ldsm stream.
DEVINL void mma16816(float* c, uint32_t a0, uint32_t a1, uint32_t a2, uint32_t a3,
                     uint32_t b0, uint32_t b1) {
    asm("mma.sync.aligned.m16n8k16.row.col.f32.f16.f16.f32 "
        "{%0,%1,%2,%3}, {%4,%5,%6,%7}, {%8,%9}, {%0,%1,%2,%3};"
        : "+f"(c[0]), "+f"(c[1]), "+f"(c[2]), "+f"(c[3])
        : "r"(a0), "r"(a1), "r"(a2), "r"(a3), "r"(b0), "r"(b1));
}

// ldsm group address within a W stage: group n (0..15)
DEVINL uint32_t gaddr(uint32_t wbu, int n) {
    return wbu + (uint32_t)(n >> 3) * 10240u + (uint32_t)((n >> 2) & 1) * 32u +
           (uint32_t)(n & 3) * 1280u;
}

// ============================================================================
// prep: fp32 W -> fp16 scratch
// ============================================================================
__global__ void cin_w2h(const float* __restrict__ W0,
                        const float* __restrict__ W1,
                        const float* __restrict__ W2) {
    int i = blockIdx.x * blockDim.x + threadIdx.x;
    constexpr int S0 = 128 * 1024;
    constexpr int S1 = 128 * 4096;
    if (i < S0)               g_W0h[i] = __float2half_rn(W0[i]);
    else if (i < S0 + S1)     g_W1h[i - S0] = __float2half_rn(W1[i - S0]);
    else if (i < S0 + 2 * S1) g_W2h[i - S0 - S1] = __float2half_rn(W2[i - S0 - S1]);
}

// W chunk-64 fetch: 2 sub-chunks of 32 k-cols; thread -> row tid>>2, seg tid&3
DEVINL void issue_w64(int gc, uint32_t wdst, int tid) {
    const __half* src; int kw;
    if (gc < 16)      { src = g_W0h + gc * 64;         kw = 1024; }
    else if (gc < 80) { src = g_W1h + (gc - 16) * 64;  kw = 4096; }
    else              { src = g_W2h + (gc - 80) * 64;  kw = 4096; }
    int r = tid >> 2, j = tid & 3;
    const __half* s0 = src + (size_t)r * kw + j * 8;
    uint32_t d0 = wdst + (uint32_t)r * 80 + (uint32_t)j * 16;
    cp_async16(d0, s0);
    cp_async16(d0 + 10240u, s0 + 32);
    cp_commit();
}

// ============================================================================
// main fused kernel: 1 CTA = 4 batches (256 n-rows x 128 o), 3 layers + score
// ============================================================================
__global__ __launch_bounds__(THREADS, 1)
void cin_main(const float* __restrict__ x0g,
              const float* __restrict__ bias0,
              const float* __restrict__ bias1,
              const float* __restrict__ bias2,
              const float* __restrict__ lwp,
              const float* __restrict__ lbp,
              float* __restrict__ outp) {
    extern __shared__ char smemc[];
    const uint32_t sb = smem_u32(smemc);
    const int tid  = threadIdx.x;
    const int w    = tid >> 5;
    const int lane = tid & 31;
    const int b_base = blockIdx.x * 4;

    // prefetch chunks 0 and 1 into stages 0 and 1
    issue_w64(0, sb + SM_W, tid);
    issue_w64(1, sb + SM_W + W_STAGE, tid);

    // bias / lw to smem
    {
        const float* bptrs[3] = { bias0, bias1, bias2 };
        float* biasS = (float*)(smemc + SM_BIAS);
        float* lwS   = (float*)(smemc + SM_LW);
        for (int i = tid; i < 384; i += THREADS) {
            biasS[i] = bptrs[i >> 7][i & 127];
            lwS[i]   = lwp[i];
        }
    }
    if (tid < 4) ((float*)(smemc + SM_SCORE))[tid] = 0.0f;

    float* hS = (float*)(smemc + SM_H);
    // layer-0 h: h[n][m] = x0[bl][m][d],  n = bl*64 + d
    for (int i = tid; i < 256 * 32; i += THREADS) {
        int m = i >> 8, n = i & 255;
        hS[(size_t)n * H_ROWF + m] =
            x0g[(((size_t)(b_base + (n >> 6))) * 32 + m) * 64 + (n & 63)];
    }

    // ---- per-thread geometry ----
    const int wn = w & 7;           // n block (32 rows)
    const int wo = w >> 3;          // o half (64 outputs)
    const int r  = lane >> 2;
    const int q  = lane & 3;
    const int bl = wn >> 1;
    const int dbase = ((wn & 1) << 5) + r;

    // x0 as half2 registers: x0h[j][i] = {x0[2q+8i], x0[2q+8i+1]} at d_j
    __half2 x0h[4][4];
    {
        const float* xb = x0g + ((size_t)(b_base + bl) * 32) * 64;
#pragma unroll
        for (int j = 0; j < 4; j++) {
            int dj = dbase + 8 * j;
#pragma unroll
            for (int i = 0; i < 4; i++) {
                int m = 2 * q + 8 * i;
                x0h[j][i] = __floats2half2_rn(xb[(size_t)m * 64 + dj],
                                              xb[(size_t)(m + 1) * 64 + dj]);
            }
        }
    }

    // h row pointers (rows n_j = 32*wn + r + 8j)
    float* hrow0 = hS + (size_t)(32 * wn + r) * H_ROWF;
    float* hrow1 = hrow0 + 8 * H_ROWF;
    float* hrow2 = hrow0 + 16 * H_ROWF;
    float* hrow3 = hrow0 + 24 * H_ROWF;

    // ldmatrix fragment base (within this warp's 64-o half)
    const int mi = lane >> 3;
    const uint32_t lm_base = (uint32_t)(wo * 5120 +
                             ((mi >> 1) * 8 + (lane & 7)) * 80 + (mi & 1) * 16);

    float acc[16][4];
#pragma unroll
    for (int t = 0; t < 16; t++)
#pragma unroll
        for (int c = 0; c < 4; c++) acc[t][c] = 0.0f;

    float score = 0.0f;
    int gc = 0;
    __syncthreads();   // h init + score init visible

    // per-chunk compute: k-rows hh = 2*chl, 2*chl+1; ldsm pipelined 1 group ahead
    auto compute_chunk = [&](int chl, uint32_t wbu) {
        float2 hf0 = *(const float2*)(hrow0 + 2 * chl);
        float2 hf1 = *(const float2*)(hrow1 + 2 * chl);
        float2 hf2 = *(const float2*)(hrow2 + 2 * chl);
        float2 hf3 = *(const float2*)(hrow3 + 2 * chl);
        __half2 hb[4][2];
        hb[0][0] = __half2half2(__float2half_rn(hf0.x));
        hb[0][1] = __half2half2(__float2half_rn(hf0.y));
        hb[1][0] = __half2half2(__float2half_rn(hf1.x));
        hb[1][1] = __half2half2(__float2half_rn(hf1.y));
        hb[2][0] = __half2half2(__float2half_rn(hf2.x));
        hb[2][1] = __half2half2(__float2half_rn(hf2.y));
        hb[3][0] = __half2half2(__float2half_rn(hf3.x));
        hb[3][1] = __half2half2(__float2half_rn(hf3.y));

        uint32_t bb[2][4];
        ldsm_x4(bb[0], gaddr(wbu, 0));          // prime group 0

#pragma unroll
        for (int s = 0; s < 4; s++) {
            const int sub = s >> 1;      // which k-row of the pair
            const int sh  = s & 1;       // m half: [0,16) or [16,32)
            uint32_t a00 = h2u(__hmul2(hb[0][sub], x0h[0][2 * sh]));
            uint32_t a01 = h2u(__hmul2(hb[1][sub], x0h[1][2 * sh]));
            uint32_t a02 = h2u(__hmul2(hb[0][sub], x0h[0][2 * sh + 1]));
            uint32_t a03 = h2u(__hmul2(hb[1][sub], x0h[1][2 * sh + 1]));
            uint32_t a10 = h2u(__hmul2(hb[2][sub], x0h[2][2 * sh]));
            uint32_t a11 = h2u(__hmul2(hb[3][sub], x0h[3][2 * sh]));
            uint32_t a12 = h2u(__hmul2(hb[2][sub], x0h[2][2 * sh + 1]));
            uint32_t a13 = h2u(__hmul2(hb[3][sub], x0h[3][2 * sh + 1]));
#pragma unroll
            for (int g = 0; g < 4; g++) {
                const int n = 4 * s + g;
                if (n + 1 < 16) ldsm_x4(bb[(n + 1) & 1], gaddr(wbu, n + 1));
                const uint32_t* b = bb[n & 1];
                mma16816(acc[2 * g],         a00, a01, a02, a03, b[0], b[1]);
                mma16816(acc[2 * g + 1],     a00, a01, a02, a03, b[2], b[3]);
                mma16816(acc[8 + 2 * g],     a10, a11, a12, a13, b[0], b[1]);
                mma16816(acc[8 + 2 * g + 1], a10, a11, a12, a13, b[2], b[3]);
            }
        }
    };

    for (int lay = 0; lay < 3; lay++) {
        const int npair = (lay == 0) ? 8 : 32;     // chunk pairs per layer
        for (int pr = 0; pr < npair; pr++, gc += 2) {
            cp_wait0();
            __syncthreads();     // stages gc%4,(gc+1)%4 visible; pair gc-2 done
            if (gc + 2 < NCH64)
                issue_w64(gc + 2,
                          sb + SM_W + (uint32_t)((gc + 2) & 3) * W_STAGE, tid);
            if (gc + 3 < NCH64)
                issue_w64(gc + 3,
                          sb + SM_W + (uint32_t)((gc + 3) & 3) * W_STAGE, tid);

            compute_chunk(2 * pr,
                          sb + SM_W + (uint32_t)(gc & 3) * W_STAGE + lm_base);
            compute_chunk(2 * pr + 1,
                          sb + SM_W + (uint32_t)((gc + 1) & 3) * W_STAGE + lm_base);
        }

        // -------- epilogue --------
        __syncthreads();   // all warps done reading h for this layer
        {
            const float* biasS = (const float*)(smemc + SM_BIAS) + lay * 128;
            const float* lwS   = (const float*)(smemc + SM_LW) + lay * 128;
            float sc = 0.0f;
#pragma unroll
            for (int T = 0; T < 2; T++) {
                float* ha  = T ? hrow2 : hrow0;
                float* hb2 = T ? hrow3 : hrow1;
#pragma unroll
                for (int go = 0; go < 8; go++) {
                    const int t = 8 * T + go;
                    const int o = 64 * wo + 8 * go + 2 * q;
                    const float bv0 = biasS[o], bv1 = biasS[o + 1];
                    float v00 = fmaxf(acc[t][0] + bv0, 0.0f);
                    float v01 = fmaxf(acc[t][1] + bv1, 0.0f);
                    float v10 = fmaxf(acc[t][2] + bv0, 0.0f);
                    float v11 = fmaxf(acc[t][3] + bv1, 0.0f);
                    sc += (v00 + v10) * lwS[o] + (v01 + v11) * lwS[o + 1];
                    if (lay < 2) {
                        *(float2*)(ha + o)  = make_float2(v00, v01);
                        *(float2*)(hb2 + o) = make_float2(v10, v11);
                    }
                    acc[t][0] = acc[t][1] = acc[t][2] = acc[t][3] = 0.0f;
                }
            }
            score += sc;
        }
        // h writes ordered before next layer's reads by next pair's barrier
    }

    // warp-reduce score, accumulate per-batch
#pragma unroll
    for (int off = 16; off; off >>= 1)
        score += __shfl_xor_sync(0xFFFFFFFFu, score, off);
    if (lane == 0) atomicAdd((float*)(smemc + SM_SCORE) + bl, score);
    __syncthreads();

    if (tid < 4) outp[b_base + tid] = ((float*)(smemc + SM_SCORE))[tid] + lbp[0];
}

extern "C" void kernel_launch(void* const* d_in, const int* in_sizes, int n_in,
                              void* d_out, int out_size) {
    const float* x0 = (const float*)d_in[0];
    const float* W0 = (const float*)d_in[1];
    const float* b0 = (const float*)d_in[2];
    const float* W1 = (const float*)d_in[3];
    const float* b1 = (const float*)d_in[4];
    const float* W2 = (const float*)d_in[5];
    const float* b2 = (const float*)d_in[6];
    const float* lw = (const float*)d_in[7];
    const float* lb = (const float*)d_in[8];
    float* outp = (float*)d_out;

    constexpr int TOTW = 128 * (1024 + 4096 + 4096);
    cin_w2h<<<(TOTW + 1023) / 1024, 1024>>>(W0, W1, W2);

    static_assert(SMEM_BYTES <= 227 * 1024, "smem");
    cudaFuncSetAttribute(cin_main, cudaFuncAttributeMaxDynamicSharedMemorySize,
                         SMEM_BYTES);
    cin_main<<<NCTA, THREADS, SMEM_BYTES>>>(x0, b0, b1, b2, lw, lb, outp);
}